// round 1
// baseline (speedup 1.0000x reference)
#include <cuda_runtime.h>

#define BFc   116
#define HWs   3136
#define NBATCH 64
#define CTOT  232
#define EPSc  1e-5f

// ---------------- scratch (static device globals; no allocation) ----------------
__device__ float g_h1[(size_t)NBATCH * BFc * HWs];   // after conv1+bn1+prelu
__device__ float g_h2[(size_t)NBATCH * BFc * HWs];   // after dw+bn2
__device__ float g_wt1[BFc * 128];                   // K-major, bn1-scaled, o padded to 128
__device__ float g_wt2[BFc * 128];                   // K-major, bn3-scaled
__device__ float g_sh1[BFc];
__device__ float g_sh2[BFc];

// ---------------- packed f32x2 helpers ----------------
__device__ __forceinline__ unsigned long long ffma2(unsigned long long a,
                                                    unsigned long long b,
                                                    unsigned long long c) {
    unsigned long long d;
    asm("fma.rn.f32x2 %0, %1, %2, %3;" : "=l"(d) : "l"(a), "l"(b), "l"(c));
    return d;
}
__device__ __forceinline__ unsigned long long dup2(float x) {
    unsigned long long d;
    asm("mov.b64 %0, {%1, %1};" : "=l"(d) : "f"(x));
    return d;
}
__device__ __forceinline__ float2 unpack2(unsigned long long v) {
    float2 r;
    asm("mov.b64 {%0, %1}, %2;" : "=f"(r.x), "=f"(r.y) : "l"(v));
    return r;
}

// ---------------- prep: fold BN into transposed weights ----------------
// wt[c*128 + o] = w[o*116 + c] * g[o]*rsqrt(v[o]+eps);  shifts[o] = b[o]-m[o]*scale
__global__ void prep_w_kernel(const float* __restrict__ w,
                              const float* __restrict__ bng,
                              const float* __restrict__ bnb,
                              const float* __restrict__ bnm,
                              const float* __restrict__ bnv,
                              float* __restrict__ wt,
                              float* __restrict__ shifts) {
    int i = blockIdx.x * 256 + threadIdx.x;
    if (i >= BFc * 128) return;
    int c = i >> 7;
    int o = i & 127;
    float val = 0.f;
    if (o < BFc) {
        float s = bng[o] * rsqrtf(bnv[o] + EPSc);
        val = w[o * BFc + c] * s;
    }
    wt[i] = val;
    if (i < BFc) {
        float s = bng[i] * rsqrtf(bnv[i] + EPSc);
        shifts[i] = bnb[i] - bnm[i] * s;
    }
}

// ---------------- shuffle-copy: out[b][2k] = x[b][k] ----------------
__global__ void copy_x1_kernel(const float* __restrict__ x, float* __restrict__ out) {
    size_t i = (size_t)blockIdx.x * 256 + threadIdx.x;   // over 64*116*784 float4
    if (i >= (size_t)NBATCH * BFc * (HWs / 4)) return;
    int p4 = (int)(i % (HWs / 4));
    int bk = (int)(i / (HWs / 4));
    int k = bk % BFc;
    int b = bk / BFc;
    const float4* s = (const float4*)(x + ((size_t)b * CTOT + k) * HWs) + p4;
    float4* d = (float4*)(out + ((size_t)b * CTOT + 2 * k) * HWs) + p4;
    *d = *s;
}

// ---------------- fused 1x1 conv GEMM + BN(shift) + PReLU ----------------
// Block: M=116(pad128) out-ch x N=64 pixels. 256 threads, micro-tile 8(o)x4(p).
// FIRST: in = x (offset to x2, batch stride 232*HW), dst = g_h1 (dense).
// !FIRST: in = g_h2 (dense), dst = out at channel 2*o+1 (shuffle odd).
template<bool FIRST>
__global__ __launch_bounds__(256, 2)
void conv1x1_fused(const float* __restrict__ in, const float* __restrict__ wt,
                   const float* __restrict__ shifts, const float* __restrict__ alpha,
                   float* __restrict__ dst)
{
    extern __shared__ float smem[];
    float* Wsm = smem;                  // [116][128]  K-major
    float* Xsm = smem + BFc * 128;      // [116][64]
    float* Ssm = Xsm + BFc * 64;        // [116] shifts

    const int tid = threadIdx.x;
    const int b  = blockIdx.y;
    const int p0 = blockIdx.x * 64;

    // load pre-scaled transposed W (coalesced, conflict-free)
    {
        float4* Wsm4 = (float4*)Wsm;
        const float4* wt4 = (const float4*)wt;
        #pragma unroll
        for (int i = tid; i < BFc * 32; i += 256) Wsm4[i] = wt4[i];
    }
    // load X tile (64 contiguous pixels x 116 channels)
    {
        const float* src = FIRST
            ? in + ((size_t)b * CTOT + BFc) * HWs + p0
            : in + ((size_t)b * BFc) * HWs + p0;
        float4* Xsm4 = (float4*)Xsm;
        #pragma unroll
        for (int i = tid; i < BFc * 16; i += 256) {
            int c  = i >> 4;
            int q4 = i & 15;
            Xsm4[i] = *(const float4*)(src + (size_t)c * HWs + q4 * 4);
        }
    }
    if (tid < BFc) Ssm[tid] = shifts[tid];
    __syncthreads();

    const int tx = tid & 15;    // pixel group
    const int ty = tid >> 4;    // out-channel group
    const int o0 = ty * 8;
    const int pp = tx * 4;

    unsigned long long acc[4][4];
    #pragma unroll
    for (int i = 0; i < 4; i++)
        #pragma unroll
        for (int j = 0; j < 4; j++) acc[i][j] = 0ull;

    const float* wrow = Wsm + o0;
    const float* xrow = Xsm + pp;

    #pragma unroll 4
    for (int k = 0; k < BFc; k++) {
        ulonglong2 wa = *(const ulonglong2*)(wrow + k * 128);
        ulonglong2 wb = *(const ulonglong2*)(wrow + k * 128 + 4);
        float4 xv = *(const float4*)(xrow + k * 64);
        unsigned long long wv0 = wa.x, wv1 = wa.y, wv2 = wb.x, wv3 = wb.y;
        unsigned long long x0 = dup2(xv.x), x1 = dup2(xv.y),
                           x2 = dup2(xv.z), x3 = dup2(xv.w);
        acc[0][0] = ffma2(wv0, x0, acc[0][0]);
        acc[0][1] = ffma2(wv0, x1, acc[0][1]);
        acc[0][2] = ffma2(wv0, x2, acc[0][2]);
        acc[0][3] = ffma2(wv0, x3, acc[0][3]);
        acc[1][0] = ffma2(wv1, x0, acc[1][0]);
        acc[1][1] = ffma2(wv1, x1, acc[1][1]);
        acc[1][2] = ffma2(wv1, x2, acc[1][2]);
        acc[1][3] = ffma2(wv1, x3, acc[1][3]);
        acc[2][0] = ffma2(wv2, x0, acc[2][0]);
        acc[2][1] = ffma2(wv2, x1, acc[2][1]);
        acc[2][2] = ffma2(wv2, x2, acc[2][2]);
        acc[2][3] = ffma2(wv2, x3, acc[2][3]);
        acc[3][0] = ffma2(wv3, x0, acc[3][0]);
        acc[3][1] = ffma2(wv3, x1, acc[3][1]);
        acc[3][2] = ffma2(wv3, x2, acc[3][2]);
        acc[3][3] = ffma2(wv3, x3, acc[3][3]);
    }

    const float al = __ldg(alpha);

    #pragma unroll
    for (int i = 0; i < 4; i++) {
        float2 u0 = unpack2(acc[i][0]);
        float2 u1 = unpack2(acc[i][1]);
        float2 u2 = unpack2(acc[i][2]);
        float2 u3 = unpack2(acc[i][3]);
        #pragma unroll
        for (int half = 0; half < 2; half++) {
            int o = o0 + 2 * i + half;
            if (o < BFc) {
                float sh = Ssm[o];
                float v0 = (half ? u0.y : u0.x) + sh;
                float v1 = (half ? u1.y : u1.x) + sh;
                float v2 = (half ? u2.y : u2.x) + sh;
                float v3 = (half ? u3.y : u3.x) + sh;
                v0 = v0 >= 0.f ? v0 : al * v0;
                v1 = v1 >= 0.f ? v1 : al * v1;
                v2 = v2 >= 0.f ? v2 : al * v2;
                v3 = v3 >= 0.f ? v3 : al * v3;
                float* dptr = FIRST
                    ? dst + ((size_t)b * BFc + o) * HWs + p0 + pp
                    : dst + ((size_t)b * CTOT + 2 * o + 1) * HWs + p0 + pp;
                *(float4*)dptr = make_float4(v0, v1, v2, v3);
            }
        }
    }
}

// ---------------- depthwise 3x3 + BN2 (no activation) ----------------
__global__ __launch_bounds__(256)
void dwconv_kernel(const float* __restrict__ h1, const float* __restrict__ wdw,
                   const float* __restrict__ bng, const float* __restrict__ bnb,
                   const float* __restrict__ bnm, const float* __restrict__ bnv,
                   float* __restrict__ h2)
{
    __shared__ float tile[58 * 58];
    const int plane = blockIdx.x;          // b*116 + c
    const int c = plane % BFc;
    const float* src = h1 + (size_t)plane * HWs;
    float* dstp = h2 + (size_t)plane * HWs;

    for (int i = threadIdx.x; i < 58 * 58; i += 256) {
        int y = i / 58, x = i - y * 58;
        int yy = y - 1, xx = x - 1;
        float val = 0.f;
        if (yy >= 0 && yy < 56 && xx >= 0 && xx < 56)
            val = src[yy * 56 + xx];
        tile[i] = val;
    }

    const float scale = bng[c] * rsqrtf(bnv[c] + EPSc);
    const float shift = bnb[c] - bnm[c] * scale;
    float w[9];
    #pragma unroll
    for (int j = 0; j < 9; j++) w[j] = wdw[c * 9 + j] * scale;

    __syncthreads();

    for (int i = threadIdx.x; i < HWs; i += 256) {
        int y = i / 56, x = i - y * 56;
        const float* t = tile + y * 58 + x;
        float s = shift;
        s += t[0]        * w[0];
        s += t[1]        * w[1];
        s += t[2]        * w[2];
        s += t[58]       * w[3];
        s += t[59]       * w[4];
        s += t[60]       * w[5];
        s += t[116]      * w[6];
        s += t[117]      * w[7];
        s += t[118]      * w[8];
        dstp[i] = s;
    }
}

// ---------------- launch ----------------
extern "C" void kernel_launch(void* const* d_in, const int* in_sizes, int n_in,
                              void* d_out, int out_size) {
    const float* x      = (const float*)d_in[0];
    const float* w2     = (const float*)d_in[1];
    const float* bn1_g  = (const float*)d_in[2];
    const float* bn1_b  = (const float*)d_in[3];
    const float* bn1_m  = (const float*)d_in[4];
    const float* bn1_v  = (const float*)d_in[5];
    const float* alpha1 = (const float*)d_in[6];
    const float* wdw    = (const float*)d_in[7];
    const float* bn2_g  = (const float*)d_in[8];
    const float* bn2_b  = (const float*)d_in[9];
    const float* bn2_m  = (const float*)d_in[10];
    const float* bn2_v  = (const float*)d_in[11];
    const float* w3     = (const float*)d_in[12];
    const float* bn3_g  = (const float*)d_in[13];
    const float* bn3_b  = (const float*)d_in[14];
    const float* bn3_m  = (const float*)d_in[15];
    const float* bn3_v  = (const float*)d_in[16];
    const float* alpha2 = (const float*)d_in[17];
    float* out = (float*)d_out;

    float *h1, *h2, *wt1, *wt2, *sh1, *sh2;
    cudaGetSymbolAddress((void**)&h1,  g_h1);
    cudaGetSymbolAddress((void**)&h2,  g_h2);
    cudaGetSymbolAddress((void**)&wt1, g_wt1);
    cudaGetSymbolAddress((void**)&wt2, g_wt2);
    cudaGetSymbolAddress((void**)&sh1, g_sh1);
    cudaGetSymbolAddress((void**)&sh2, g_sh2);

    const int smem_bytes = (BFc * 128 + BFc * 64 + BFc) * 4;   // 89552
    cudaFuncSetAttribute(conv1x1_fused<true>,
                         cudaFuncAttributeMaxDynamicSharedMemorySize, smem_bytes);
    cudaFuncSetAttribute(conv1x1_fused<false>,
                         cudaFuncAttributeMaxDynamicSharedMemorySize, smem_bytes);

    // weight prep (tiny)
    prep_w_kernel<<<(BFc * 128 + 255) / 256, 256>>>(w2, bn1_g, bn1_b, bn1_m, bn1_v, wt1, sh1);
    prep_w_kernel<<<(BFc * 128 + 255) / 256, 256>>>(w3, bn3_g, bn3_b, bn3_m, bn3_v, wt2, sh2);

    // shuffle even channels: out[b][2k] = x[b][k]
    {
        size_t n4 = (size_t)NBATCH * BFc * (HWs / 4);
        copy_x1_kernel<<<(unsigned)((n4 + 255) / 256), 256>>>(x, out);
    }

    // conv1 + bn1 + prelu -> h1
    conv1x1_fused<true><<<dim3(HWs / 64, NBATCH), 256, smem_bytes>>>(x, wt1, sh1, alpha1, h1);

    // dw3x3 + bn2 -> h2
    dwconv_kernel<<<NBATCH * BFc, 256>>>(h1, wdw, bn2_g, bn2_b, bn2_m, bn2_v, h2);

    // conv2 + bn3 + prelu -> out odd channels (shuffle)
    conv1x1_fused<false><<<dim3(HWs / 64, NBATCH), 256, smem_bytes>>>(h2, wt2, sh2, alpha2, out);
}

// round 3
// speedup vs baseline: 1.1610x; 1.1610x over previous
#include <cuda_runtime.h>
#include <cstdint>

#define BFc    116
#define HWs    3136
#define NBATCH 64
#define CTOT   232
#define EPSc   1e-5f
#define KPAD   120

// ---------------- scratch ----------------
__device__ float g_h1[(size_t)NBATCH * BFc * HWs];   // prelu(bn1(conv1))
__device__ float g_h2[(size_t)NBATCH * BFc * HWs];   // raw dwconv(h1)  (bn2 folded into conv2)
__device__ float g_wt1[128 * 128];                   // [o][k] bn1-scaled, tf32-rounded, padded
__device__ float g_wt2[128 * 128];                   // [o][k] bn3*bn2-scaled, tf32-rounded
__device__ float g_sh1[128];
__device__ float g_sh2[128];

// ---------------- helpers ----------------
__device__ __forceinline__ float tf32r(float x) {
    uint32_t u;
    asm("cvt.rna.tf32.f32 %0, %1;" : "=r"(u) : "f"(x));
    return __uint_as_float(u);
}

__device__ __forceinline__ void mma_tf32(float* d, const uint32_t* a, const uint32_t* b) {
    asm volatile(
        "mma.sync.aligned.m16n8k8.row.col.f32.tf32.tf32.f32 "
        "{%0,%1,%2,%3}, {%4,%5,%6,%7}, {%8,%9}, {%0,%1,%2,%3};"
        : "+f"(d[0]), "+f"(d[1]), "+f"(d[2]), "+f"(d[3])
        : "r"(a[0]), "r"(a[1]), "r"(a[2]), "r"(a[3]), "r"(b[0]), "r"(b[1]));
}

// ---------------- prep kernels ----------------
__global__ void prep_w1(const float* __restrict__ w, const float* __restrict__ bng,
                        const float* __restrict__ bnb, const float* __restrict__ bnm,
                        const float* __restrict__ bnv, float* __restrict__ wt,
                        float* __restrict__ sh) {
    int i = blockIdx.x * 256 + threadIdx.x;
    if (i >= 128 * 128) return;
    int o = i >> 7, k = i & 127;
    float val = 0.f;
    if (o < BFc && k < BFc) {
        float s = bng[o] * rsqrtf(bnv[o] + EPSc);
        val = tf32r(w[o * BFc + k] * s);
    }
    wt[i] = val;
    if (i < 128) {
        float shv = 0.f;
        if (i < BFc) {
            float s = bng[i] * rsqrtf(bnv[i] + EPSc);
            shv = bnb[i] - bnm[i] * s;
        }
        sh[i] = shv;
    }
}

// conv2 weights: wt2[o][k] = w3[o][k]*s3[o]*s2[k];  sh2[o] = t3[o] + s3[o]*sum_k w3[o][k]*t2[k]
__global__ void prep_w2(const float* __restrict__ w3,
                        const float* __restrict__ bn2g, const float* __restrict__ bn2b,
                        const float* __restrict__ bn2m, const float* __restrict__ bn2v,
                        const float* __restrict__ bn3g, const float* __restrict__ bn3b,
                        const float* __restrict__ bn3m, const float* __restrict__ bn3v,
                        float* __restrict__ wt, float* __restrict__ sh) {
    __shared__ float s2s[BFc], t2s[BFc];
    int tid = threadIdx.x;                // 128 threads, single block
    if (tid < BFc) {
        float s2 = bn2g[tid] * rsqrtf(bn2v[tid] + EPSc);
        s2s[tid] = s2;
        t2s[tid] = bn2b[tid] - bn2m[tid] * s2;
    }
    __syncthreads();
    int o = tid;
    float s3 = 0.f, t3 = 0.f;
    if (o < BFc) {
        s3 = bn3g[o] * rsqrtf(bn3v[o] + EPSc);
        t3 = bn3b[o] - bn3m[o] * s3;
    }
    float acc = 0.f;
    for (int k = 0; k < 128; k++) {
        float val = 0.f;
        if (o < BFc && k < BFc) {
            float wv = w3[o * BFc + k];
            val = tf32r(wv * s3 * s2s[k]);
            acc += wv * t2s[k];
        }
        wt[o * 128 + k] = val;
    }
    sh[o] = (o < BFc) ? (t3 + s3 * acc) : 0.f;
}

// ---------------- shuffle-copy: out[b][2k] = x[b][k] ----------------
__global__ void copy_x1_kernel(const float* __restrict__ x, float* __restrict__ out) {
    size_t i = (size_t)blockIdx.x * 256 + threadIdx.x;
    if (i >= (size_t)NBATCH * BFc * (HWs / 4)) return;
    int p4 = (int)(i % (HWs / 4));
    int bk = (int)(i / (HWs / 4));
    int k = bk % BFc;
    int b = bk / BFc;
    const float4* s = (const float4*)(x + ((size_t)b * CTOT + k) * HWs) + p4;
    float4* d = (float4*)(out + ((size_t)b * CTOT + 2 * k) * HWs) + p4;
    *d = *s;
}

// ---------------- mma.sync tf32 fused 1x1 conv ----------------
// D[128 ch][64 px] = Wt[128][120] * X[120][64];  8 warps as 4(M)x2(N), warp tile 32x32.
#define WPITCH 132      // floats; 132 % 32 == 4  -> A-load banks 4*gid+tig (distinct)
#define XPITCH 72       // floats; 72 % 32 == 8   -> B-load banks 8*tig+gid (distinct)
#define SMEM_FLOATS (128 * WPITCH + KPAD * XPITCH + 128)

template<bool FIRST>
__global__ __launch_bounds__(256, 2)
void conv1x1_mma(const float* __restrict__ in, const float* __restrict__ wt,
                 const float* __restrict__ shifts, const float* __restrict__ alpha,
                 float* __restrict__ dst)
{
    extern __shared__ float smem[];
    float* Wsm = smem;                        // [128][WPITCH]
    float* Xsm = smem + 128 * WPITCH;         // [KPAD][XPITCH]
    float* Ssm = Xsm + KPAD * XPITCH;         // [128]

    const int tid = threadIdx.x;
    const int b = blockIdx.y;
    const int p0 = blockIdx.x * 64;

    // ---- fill W smem (pre-rounded tf32 weights), 128 rows x 30 float4 ----
    #pragma unroll 4
    for (int i = tid; i < 128 * 30; i += 256) {
        int o = i / 30, k4 = i % 30;
        float4 v = *(const float4*)(wt + o * 128 + k4 * 4);
        *(float4*)(Wsm + o * WPITCH + k4 * 4) = v;
    }
    // ---- fill X smem (tf32-rounded), KPAD rows x 16 float4 ----
    {
        const float* src = FIRST
            ? in + ((size_t)b * CTOT + BFc) * HWs + p0
            : in + ((size_t)b * BFc) * HWs + p0;
        #pragma unroll 4
        for (int i = tid; i < KPAD * 16; i += 256) {
            int k = i >> 4, q = i & 15;
            float4 v = make_float4(0.f, 0.f, 0.f, 0.f);
            if (k < BFc) v = *(const float4*)(src + (size_t)k * HWs + q * 4);
            v.x = tf32r(v.x); v.y = tf32r(v.y); v.z = tf32r(v.z); v.w = tf32r(v.w);
            *(float4*)(Xsm + k * XPITCH + q * 4) = v;
        }
    }
    if (tid < 128) Ssm[tid] = shifts[tid];
    __syncthreads();

    const int wid = tid >> 5, lane = tid & 31;
    const int gid = lane >> 2, tig = lane & 3;
    const int o0 = (wid >> 1) * 32;
    const int pw = (wid & 1) * 32;

    float acc[2][4][4];
    #pragma unroll
    for (int mi = 0; mi < 2; mi++)
        #pragma unroll
        for (int ni = 0; ni < 4; ni++)
            #pragma unroll
            for (int r = 0; r < 4; r++) acc[mi][ni][r] = 0.f;

    #pragma unroll
    for (int ks = 0; ks < KPAD / 8; ks++) {
        const int k0 = ks * 8;
        uint32_t a[2][4];
        #pragma unroll
        for (int mi = 0; mi < 2; mi++) {
            const float* wp = Wsm + (o0 + mi * 16 + gid) * WPITCH + k0 + tig;
            a[mi][0] = __float_as_uint(wp[0]);
            a[mi][1] = __float_as_uint(wp[8 * WPITCH]);
            a[mi][2] = __float_as_uint(wp[4]);
            a[mi][3] = __float_as_uint(wp[8 * WPITCH + 4]);
        }
        uint32_t bf[4][2];
        #pragma unroll
        for (int ni = 0; ni < 4; ni++) {
            const float* xp = Xsm + (k0 + tig) * XPITCH + pw + ni * 8 + gid;
            bf[ni][0] = __float_as_uint(xp[0]);
            bf[ni][1] = __float_as_uint(xp[4 * XPITCH]);
        }
        #pragma unroll
        for (int mi = 0; mi < 2; mi++)
            #pragma unroll
            for (int ni = 0; ni < 4; ni++)
                mma_tf32(acc[mi][ni], a[mi], bf[ni]);
    }

    // ---- epilogue: shift + PReLU, STG.64 per (o, 2px) ----
    const float al = __ldg(alpha);
    #pragma unroll
    for (int mi = 0; mi < 2; mi++) {
        #pragma unroll
        for (int half = 0; half < 2; half++) {
            const int o = o0 + mi * 16 + gid + half * 8;
            if (o < BFc) {
                const float sh = Ssm[o];
                float* dp = FIRST
                    ? dst + ((size_t)b * BFc + o) * HWs + p0
                    : dst + ((size_t)b * CTOT + 2 * o + 1) * HWs + p0;
                #pragma unroll
                for (int ni = 0; ni < 4; ni++) {
                    float c0 = acc[mi][ni][half * 2 + 0] + sh;
                    float c1 = acc[mi][ni][half * 2 + 1] + sh;
                    c0 = c0 >= 0.f ? c0 : al * c0;
                    c1 = c1 >= 0.f ? c1 : al * c1;
                    *(float2*)(dp + pw + ni * 8 + 2 * tig) = make_float2(c0, c1);
                }
            }
        }
    }
}

// ---------------- depthwise 3x3, raw (BN2 folded into conv2) ----------------
__global__ __launch_bounds__(256)
void dwconv_kernel(const float* __restrict__ h1, const float* __restrict__ wdw,
                   float* __restrict__ h2)
{
    __shared__ float tile[58 * 60];
    const int plane = blockIdx.x;          // b*116 + c
    const int c = plane % BFc;
    const float* src = h1 + (size_t)plane * HWs;
    float* dstp = h2 + (size_t)plane * HWs;

    for (int i = threadIdx.x; i < 58 * 58; i += 256) {
        int y = i / 58, x = i - y * 58;
        int yy = y - 1, xx = x - 1;
        float val = 0.f;
        if (yy >= 0 && yy < 56 && xx >= 0 && xx < 56)
            val = src[yy * 56 + xx];
        tile[y * 60 + x] = val;
    }

    float w[9];
    #pragma unroll
    for (int j = 0; j < 9; j++) w[j] = wdw[c * 9 + j];

    __syncthreads();

    for (int i = threadIdx.x; i < 784; i += 256) {
        int y = i / 14;
        int x = (i - y * 14) * 4;
        float o0 = 0.f, o1 = 0.f, o2 = 0.f, o3 = 0.f;
        #pragma unroll
        for (int rrow = 0; rrow < 3; rrow++) {
            const float* t = tile + (y + rrow) * 60 + x;
            float4 a = *(const float4*)t;
            float e4 = t[4], e5 = t[5];
            float w0 = w[3 * rrow], w1 = w[3 * rrow + 1], w2 = w[3 * rrow + 2];
            o0 += w0 * a.x + w1 * a.y + w2 * a.z;
            o1 += w0 * a.y + w1 * a.z + w2 * a.w;
            o2 += w0 * a.z + w1 * a.w + w2 * e4;
            o3 += w0 * a.w + w1 * e4 + w2 * e5;
        }
        *(float4*)(dstp + y * 56 + x) = make_float4(o0, o1, o2, o3);
    }
}

// ---------------- launch ----------------
extern "C" void kernel_launch(void* const* d_in, const int* in_sizes, int n_in,
                              void* d_out, int out_size) {
    const float* x      = (const float*)d_in[0];
    const float* w2     = (const float*)d_in[1];
    const float* bn1_g  = (const float*)d_in[2];
    const float* bn1_b  = (const float*)d_in[3];
    const float* bn1_m  = (const float*)d_in[4];
    const float* bn1_v  = (const float*)d_in[5];
    const float* alpha1 = (const float*)d_in[6];
    const float* wdw    = (const float*)d_in[7];
    const float* bn2_g  = (const float*)d_in[8];
    const float* bn2_b  = (const float*)d_in[9];
    const float* bn2_m  = (const float*)d_in[10];
    const float* bn2_v  = (const float*)d_in[11];
    const float* w3     = (const float*)d_in[12];
    const float* bn3_g  = (const float*)d_in[13];
    const float* bn3_b  = (const float*)d_in[14];
    const float* bn3_m  = (const float*)d_in[15];
    const float* bn3_v  = (const float*)d_in[16];
    const float* alpha2 = (const float*)d_in[17];
    float* out = (float*)d_out;

    float *h1, *h2, *wt1, *wt2, *sh1, *sh2;
    cudaGetSymbolAddress((void**)&h1,  g_h1);
    cudaGetSymbolAddress((void**)&h2,  g_h2);
    cudaGetSymbolAddress((void**)&wt1, g_wt1);
    cudaGetSymbolAddress((void**)&wt2, g_wt2);
    cudaGetSymbolAddress((void**)&sh1, g_sh1);
    cudaGetSymbolAddress((void**)&sh2, g_sh2);

    const int smem_bytes = SMEM_FLOATS * 4;   // 102656
    cudaFuncSetAttribute(conv1x1_mma<true>,
                         cudaFuncAttributeMaxDynamicSharedMemorySize, smem_bytes);
    cudaFuncSetAttribute(conv1x1_mma<false>,
                         cudaFuncAttributeMaxDynamicSharedMemorySize, smem_bytes);

    prep_w1<<<64, 256>>>(w2, bn1_g, bn1_b, bn1_m, bn1_v, wt1, sh1);
    prep_w2<<<1, 128>>>(w3, bn2_g, bn2_b, bn2_m, bn2_v,
                        bn3_g, bn3_b, bn3_m, bn3_v, wt2, sh2);

    {
        size_t n4 = (size_t)NBATCH * BFc * (HWs / 4);
        copy_x1_kernel<<<(unsigned)((n4 + 255) / 256), 256>>>(x, out);
    }

    conv1x1_mma<true><<<dim3(HWs / 64, NBATCH), 256, smem_bytes>>>(x, wt1, sh1, alpha1, h1);

    dwconv_kernel<<<NBATCH * BFc, 256>>>(h1, wdw, h2);

    conv1x1_mma<false><<<dim3(HWs / 64, NBATCH), 256, smem_bytes>>>(h2, wt2, sh2, alpha2, out);
}

// round 7
// speedup vs baseline: 1.4368x; 1.2375x over previous
#include <cuda_runtime.h>
#include <cstdint>

#define BFc    116
#define HWs    3136
#define NBATCH 64
#define CTOT   232
#define EPSc   1e-5f
#define KPAD   120
#define TTILE  7          // pixel tiles per block
#define NT     64         // pixels per tile

// ---------------- scratch ----------------
__device__ float g_h1[(size_t)NBATCH * BFc * HWs];
__device__ float g_h2[(size_t)NBATCH * BFc * HWs];
__device__ float g_wt1[128 * 128];
__device__ float g_wt2[128 * 128];
__device__ float g_sh1[128];
__device__ float g_sh2[128];

// ---------------- helpers ----------------
__device__ __forceinline__ float tf32r(float x) {
    uint32_t u;
    asm("cvt.rna.tf32.f32 %0, %1;" : "=r"(u) : "f"(x));
    return __uint_as_float(u);
}
__device__ __forceinline__ uint32_t smem_u32(const void* p) {
    uint32_t a;
    asm("{ .reg .u64 t; cvta.to.shared.u64 t, %1; cvt.u32.u64 %0, t; }" : "=r"(a) : "l"(p));
    return a;
}
__device__ __forceinline__ void cp_async16(uint32_t dst, const void* src) {
    asm volatile("cp.async.cg.shared.global [%0], [%1], 16;" :: "r"(dst), "l"(src));
}
#define CP_COMMIT() asm volatile("cp.async.commit_group;" ::: "memory")

__device__ __forceinline__ void mma_tf32(float* d, const uint32_t* a, const uint32_t* b) {
    asm volatile(
        "mma.sync.aligned.m16n8k8.row.col.f32.tf32.tf32.f32 "
        "{%0,%1,%2,%3}, {%4,%5,%6,%7}, {%8,%9}, {%0,%1,%2,%3};"
        : "+f"(d[0]), "+f"(d[1]), "+f"(d[2]), "+f"(d[3])
        : "r"(a[0]), "r"(a[1]), "r"(a[2]), "r"(a[3]), "r"(b[0]), "r"(b[1]));
}

// ---------------- prep kernels ----------------
__global__ void prep_w1(const float* __restrict__ w, const float* __restrict__ bng,
                        const float* __restrict__ bnb, const float* __restrict__ bnm,
                        const float* __restrict__ bnv, float* __restrict__ wt,
                        float* __restrict__ sh) {
    int i = blockIdx.x * 256 + threadIdx.x;
    if (i >= 128 * 128) return;
    int o = i >> 7, k = i & 127;
    float val = 0.f;
    if (o < BFc && k < BFc) {
        float s = bng[o] * rsqrtf(bnv[o] + EPSc);
        val = tf32r(w[o * BFc + k] * s);
    }
    wt[i] = val;
    if (i < 128) {
        float shv = 0.f;
        if (i < BFc) {
            float s = bng[i] * rsqrtf(bnv[i] + EPSc);
            shv = bnb[i] - bnm[i] * s;
        }
        sh[i] = shv;
    }
}

__global__ void prep_w2(const float* __restrict__ w3,
                        const float* __restrict__ bn2g, const float* __restrict__ bn2b,
                        const float* __restrict__ bn2m, const float* __restrict__ bn2v,
                        const float* __restrict__ bn3g, const float* __restrict__ bn3b,
                        const float* __restrict__ bn3m, const float* __restrict__ bn3v,
                        float* __restrict__ wt, float* __restrict__ sh) {
    __shared__ float s2s[BFc], t2s[BFc];
    int tid = threadIdx.x;
    if (tid < BFc) {
        float s2 = bn2g[tid] * rsqrtf(bn2v[tid] + EPSc);
        s2s[tid] = s2;
        t2s[tid] = bn2b[tid] - bn2m[tid] * s2;
    }
    __syncthreads();
    int o = tid;
    float s3 = 0.f, t3 = 0.f;
    if (o < BFc) {
        s3 = bn3g[o] * rsqrtf(bn3v[o] + EPSc);
        t3 = bn3b[o] - bn3m[o] * s3;
    }
    float acc = 0.f;
    for (int k = 0; k < 128; k++) {
        float val = 0.f;
        if (o < BFc && k < BFc) {
            float wv = w3[o * BFc + k];
            val = tf32r(wv * s3 * s2s[k]);
            acc += wv * t2s[k];
        }
        wt[o * 128 + k] = val;
    }
    sh[o] = (o < BFc) ? (t3 + s3 * acc) : 0.f;
}

// ---------------- shuffle-copy: out[b][2k] = x[b][k] ----------------
__global__ void copy_x1_kernel(const float* __restrict__ x, float* __restrict__ out) {
    size_t i = (size_t)blockIdx.x * 256 + threadIdx.x;
    if (i >= (size_t)NBATCH * BFc * (HWs / 4)) return;
    int p4 = (int)(i % (HWs / 4));
    int bk = (int)(i / (HWs / 4));
    int k = bk % BFc;
    int b = bk / BFc;
    const float4* s = (const float4*)(x + ((size_t)b * CTOT + k) * HWs) + p4;
    float4* d = (float4*)(out + ((size_t)b * CTOT + 2 * k) * HWs) + p4;
    *d = *s;
}

// ---------------- pipelined mma.sync tf32 fused 1x1 conv ----------------
// Block: W[128][124] resident; loops T=7 tiles of 64 px with cp.async double buffer.
#define WPITCH 124      // 124 % 32 == 28 -> A banks (28*gid+tig) all distinct
#define XPITCH 72       // 72 % 32 == 8   -> B banks (8*tig+gid) all distinct
#define SM_W  0
#define SM_X0 (128 * WPITCH)
#define SM_X1 (SM_X0 + KPAD * XPITCH)
#define SM_S  (SM_X1 + KPAD * XPITCH)
#define SMEM_FLOATS (SM_S + 128)

template<bool FIRST>
__global__ __launch_bounds__(256, 1)
void conv1x1_mma(const float* __restrict__ in, const float* __restrict__ wt,
                 const float* __restrict__ shifts, const float* __restrict__ alpha,
                 float* __restrict__ dst)
{
    extern __shared__ float smem[];
    float* Wsm = smem + SM_W;
    float* Ssm = smem + SM_S;

    const int tid = threadIdx.x;
    const int b = blockIdx.y;
    const int base = blockIdx.x * (TTILE * NT);

    const float* src_base = FIRST
        ? in + ((size_t)b * CTOT + BFc) * HWs + base
        : in + ((size_t)b * BFc) * HWs + base;

    // zero K-pad rows (116..119) of both X buffers (never async-written)
    for (int i = tid; i < 2 * 4 * XPITCH; i += 256) {
        int buf = i / (4 * XPITCH);
        int r = i % (4 * XPITCH);
        smem[(buf ? SM_X1 : SM_X0) + (116 * XPITCH) + r] = 0.f;
    }

    // prologue: async-load tiles 0 and 1 (X streams while W fills)
    {
        uint32_t x0 = smem_u32(smem + SM_X0);
        for (int i = tid; i < BFc * 16; i += 256) {
            int k = i >> 4, q = i & 15;
            cp_async16(x0 + (uint32_t)(k * XPITCH + q * 4) * 4,
                       src_base + (size_t)k * HWs + q * 4);
        }
        CP_COMMIT();
        uint32_t x1 = smem_u32(smem + SM_X1);
        for (int i = tid; i < BFc * 16; i += 256) {
            int k = i >> 4, q = i & 15;
            cp_async16(x1 + (uint32_t)(k * XPITCH + q * 4) * 4,
                       src_base + (size_t)k * HWs + NT + q * 4);
        }
        CP_COMMIT();
    }

    // W fill (stays resident for all 7 tiles)
    #pragma unroll 4
    for (int i = tid; i < 128 * 31; i += 256) {
        int o = i / 31, k4 = i % 31;
        float4 v = *(const float4*)(wt + o * 128 + k4 * 4);
        *(float4*)(Wsm + o * WPITCH + k4 * 4) = v;
    }
    if (tid < 128) Ssm[tid] = shifts[tid];

    const int wid = tid >> 5, lane = tid & 31;
    const int gid = lane >> 2, tig = lane & 3;
    const int o0 = (wid >> 1) * 32;
    const int pw = (wid & 1) * 32;
    const float al = __ldg(alpha);

    #pragma unroll 1
    for (int t = 0; t < TTILE; t++) {
        if (t + 1 < TTILE) asm volatile("cp.async.wait_group 1;" ::: "memory");
        else               asm volatile("cp.async.wait_group 0;" ::: "memory");
        __syncthreads();

        const float* Xsm = smem + ((t & 1) ? SM_X1 : SM_X0);

        float acc[2][4][4];
        #pragma unroll
        for (int mi = 0; mi < 2; mi++)
            #pragma unroll
            for (int ni = 0; ni < 4; ni++)
                #pragma unroll
                for (int r = 0; r < 4; r++) acc[mi][ni][r] = 0.f;

        #pragma unroll
        for (int ks = 0; ks < KPAD / 8; ks++) {
            const int k0 = ks * 8;
            uint32_t a[2][4];
            #pragma unroll
            for (int mi = 0; mi < 2; mi++) {
                const float* wp = Wsm + (o0 + mi * 16 + gid) * WPITCH + k0 + tig;
                a[mi][0] = __float_as_uint(wp[0]);
                a[mi][1] = __float_as_uint(wp[8 * WPITCH]);
                a[mi][2] = __float_as_uint(wp[4]);
                a[mi][3] = __float_as_uint(wp[8 * WPITCH + 4]);
            }
            uint32_t bf[4][2];
            #pragma unroll
            for (int ni = 0; ni < 4; ni++) {
                const float* xp = Xsm + (k0 + tig) * XPITCH + pw + ni * 8 + gid;
                bf[ni][0] = __float_as_uint(xp[0]);
                bf[ni][1] = __float_as_uint(xp[4 * XPITCH]);
            }
            #pragma unroll
            for (int mi = 0; mi < 2; mi++)
                #pragma unroll
                for (int ni = 0; ni < 4; ni++)
                    mma_tf32(acc[mi][ni], a[mi], bf[ni]);
        }

        // epilogue: shift + PReLU, STG.64
        const int p0 = base + t * NT;
        #pragma unroll
        for (int mi = 0; mi < 2; mi++) {
            #pragma unroll
            for (int half = 0; half < 2; half++) {
                const int o = o0 + mi * 16 + gid + half * 8;
                if (o < BFc) {
                    const float sh = Ssm[o];
                    float* dp = FIRST
                        ? dst + ((size_t)b * BFc + o) * HWs + p0
                        : dst + ((size_t)b * CTOT + 2 * o + 1) * HWs + p0;
                    #pragma unroll
                    for (int ni = 0; ni < 4; ni++) {
                        float c0 = acc[mi][ni][half * 2 + 0] + sh;
                        float c1 = acc[mi][ni][half * 2 + 1] + sh;
                        c0 = c0 >= 0.f ? c0 : al * c0;
                        c1 = c1 >= 0.f ? c1 : al * c1;
                        *(float2*)(dp + pw + ni * 8 + 2 * tig) = make_float2(c0, c1);
                    }
                }
            }
        }

        __syncthreads();   // everyone done reading X buf t before refilling it

        if (t + 2 < TTILE) {
            float* nb = smem + ((t & 1) ? SM_X1 : SM_X0);
            uint32_t nbu = smem_u32(nb);
            const float* src_t = src_base + (t + 2) * NT;
            for (int i = tid; i < BFc * 16; i += 256) {
                int k = i >> 4, q = i & 15;
                cp_async16(nbu + (uint32_t)(k * XPITCH + q * 4) * 4,
                           src_t + (size_t)k * HWs + q * 4);
            }
            CP_COMMIT();
        }
    }
}

// ---------------- depthwise 3x3, raw (BN2 folded into conv2) ----------------
__global__ __launch_bounds__(256)
void dwconv_kernel(const float* __restrict__ h1, const float* __restrict__ wdw,
                   float* __restrict__ h2)
{
    __shared__ float tile[58 * 60];
    const int plane = blockIdx.x;
    const int c = plane % BFc;
    const float* src = h1 + (size_t)plane * HWs;
    float* dstp = h2 + (size_t)plane * HWs;

    for (int i = threadIdx.x; i < 58 * 58; i += 256) {
        int y = i / 58, x = i - y * 58;
        int yy = y - 1, xx = x - 1;
        float val = 0.f;
        if (yy >= 0 && yy < 56 && xx >= 0 && xx < 56)
            val = src[yy * 56 + xx];
        tile[y * 60 + x] = val;
    }

    float w[9];
    #pragma unroll
    for (int j = 0; j < 9; j++) w[j] = wdw[c * 9 + j];

    __syncthreads();

    for (int i = threadIdx.x; i < 784; i += 256) {
        int y = i / 14;
        int x = (i - y * 14) * 4;
        float o0 = 0.f, o1 = 0.f, o2 = 0.f, o3 = 0.f;
        #pragma unroll
        for (int rrow = 0; rrow < 3; rrow++) {
            const float* t = tile + (y + rrow) * 60 + x;
            float4 a = *(const float4*)t;
            float e4 = t[4], e5 = t[5];
            float w0 = w[3 * rrow], w1 = w[3 * rrow + 1], w2 = w[3 * rrow + 2];
            o0 += w0 * a.x + w1 * a.y + w2 * a.z;
            o1 += w0 * a.y + w1 * a.z + w2 * a.w;
            o2 += w0 * a.z + w1 * a.w + w2 * e4;
            o3 += w0 * a.w + w1 * e4 + w2 * e5;
        }
        *(float4*)(dstp + y * 56 + x) = make_float4(o0, o1, o2, o3);
    }
}

// ---------------- launch ----------------
extern "C" void kernel_launch(void* const* d_in, const int* in_sizes, int n_in,
                              void* d_out, int out_size) {
    const float* x      = (const float*)d_in[0];
    const float* w2     = (const float*)d_in[1];
    const float* bn1_g  = (const float*)d_in[2];
    const float* bn1_b  = (const float*)d_in[3];
    const float* bn1_m  = (const float*)d_in[4];
    const float* bn1_v  = (const float*)d_in[5];
    const float* alpha1 = (const float*)d_in[6];
    const float* wdw    = (const float*)d_in[7];
    const float* bn2_g  = (const float*)d_in[8];
    const float* bn2_b  = (const float*)d_in[9];
    const float* bn2_m  = (const float*)d_in[10];
    const float* bn2_v  = (const float*)d_in[11];
    const float* w3     = (const float*)d_in[12];
    const float* bn3_g  = (const float*)d_in[13];
    const float* bn3_b  = (const float*)d_in[14];
    const float* bn3_m  = (const float*)d_in[15];
    const float* bn3_v  = (const float*)d_in[16];
    const float* alpha2 = (const float*)d_in[17];
    float* out = (float*)d_out;

    float *h1, *h2, *wt1, *wt2, *sh1, *sh2;
    cudaGetSymbolAddress((void**)&h1,  g_h1);
    cudaGetSymbolAddress((void**)&h2,  g_h2);
    cudaGetSymbolAddress((void**)&wt1, g_wt1);
    cudaGetSymbolAddress((void**)&wt2, g_wt2);
    cudaGetSymbolAddress((void**)&sh1, g_sh1);
    cudaGetSymbolAddress((void**)&sh2, g_sh2);

    const int smem_bytes = SMEM_FLOATS * 4;   // ~133 KB
    cudaFuncSetAttribute(conv1x1_mma<true>,
                         cudaFuncAttributeMaxDynamicSharedMemorySize, smem_bytes);
    cudaFuncSetAttribute(conv1x1_mma<false>,
                         cudaFuncAttributeMaxDynamicSharedMemorySize, smem_bytes);

    prep_w1<<<64, 256>>>(w2, bn1_g, bn1_b, bn1_m, bn1_v, wt1, sh1);
    prep_w2<<<1, 128>>>(w3, bn2_g, bn2_b, bn2_m, bn2_v,
                        bn3_g, bn3_b, bn3_m, bn3_v, wt2, sh2);

    {
        size_t n4 = (size_t)NBATCH * BFc * (HWs / 4);
        copy_x1_kernel<<<(unsigned)((n4 + 255) / 256), 256>>>(x, out);
    }

    conv1x1_mma<true><<<dim3(TTILE, NBATCH), 256, smem_bytes>>>(x, wt1, sh1, alpha1, h1);

    dwconv_kernel<<<NBATCH * BFc, 256>>>(h1, wdw, h2);

    conv1x1_mma<false><<<dim3(TTILE, NBATCH), 256, smem_bytes>>>(h2, wt2, sh2, alpha2, out);
}